// round 13
// baseline (speedup 1.0000x reference)
#include <cuda_runtime.h>
#include <cuda_bf16.h>
#include <cstdint>
#include <math.h>

#define T_TOK 16384
#define HDIM  2048
#define FDIM  256
#define NEXP  12
#define CAP   1707
#define CAPP  1792   // 14 * 128
#define LG2T  14
#define SCAN_B 32
#define SCAN_T 256

// ---------------- scratch (device globals; no allocs allowed) ----------------
__device__ float g_rw [T_TOK * 2];
__device__ int   g_sel[T_TOK * 2];
__device__ int   g_tok[NEXP * CAPP];
__device__ float g_wgt[NEXP * CAPP];
__device__ int   g_cnt[NEXP];
__device__ int   g_agg[SCAN_B * NEXP];
__device__ int   g_readycnt;
__device__ __align__(16) uint32_t g_xt [T_TOK * HDIM];            // tf32 x, K-permuted
__device__ __align__(16) uint32_t g_h  [NEXP * CAPP * FDIM];      // tf32 h, K-permuted
__device__ __align__(16) uint32_t g_w1t[NEXP * FDIM * HDIM];      // tf32 weights, K-permuted
__device__ __align__(16) uint32_t g_w2t[NEXP * HDIM * FDIM];
__device__ __align__(16) uint32_t g_w3t[NEXP * FDIM * HDIM];

// ---------------- helpers ----------------
__device__ __forceinline__ uint32_t f2tf(float f) {
    uint32_t u;
    asm("cvt.rna.tf32.f32 %0, %1;" : "=r"(u) : "f"(f));
    return u;
}

__device__ __forceinline__ void mma_tf32(float& d0, float& d1, float& d2, float& d3,
                                         uint32_t a0, uint32_t a1, uint32_t a2, uint32_t a3,
                                         uint32_t b0, uint32_t b1) {
    asm volatile(
        "mma.sync.aligned.m16n8k8.row.col.f32.tf32.tf32.f32 "
        "{%0,%1,%2,%3}, {%4,%5,%6,%7}, {%8,%9}, {%0,%1,%2,%3};"
        : "+f"(d0), "+f"(d1), "+f"(d2), "+f"(d3)
        : "r"(a0), "r"(a1), "r"(a2), "r"(a3), "r"(b0), "r"(b1));
}

__device__ __forceinline__ uint32_t sptr(const void* p) {
    return (uint32_t)__cvta_generic_to_shared(p);
}

#define CP16(dst_u32, src_ptr) \
    asm volatile("cp.async.cg.shared.global [%0], [%1], 16;" :: "r"(dst_u32), "l"(src_ptr))
#define CP_COMMIT() asm volatile("cp.async.commit_group;")
#define CP_WAIT1()  asm volatile("cp.async.wait_group 1;")

// permuted position of column c within its 8-group: 0,4,1,5,2,6,3,7 -> 0..7
__device__ __host__ __forceinline__ int pperm(int c) {
    return ((c & 3) << 1) | ((c >> 2) & 1);
}

// ---------------- kernel A: convert+permute w1/w2/w3/x fp32 -> tf32 ----------------
// Each thread handles one 8-column group: loads 2 float4, writes 2 uint4 interleaved
// so that output positions (0..7) hold original columns (0,4,1,5,2,6,3,7).
__global__ void k_cvt_all(const float4* __restrict__ s1, uint4* __restrict__ d1,
                          const float4* __restrict__ s2, uint4* __restrict__ d2,
                          const float4* __restrict__ s3, uint4* __restrict__ d3,
                          const float4* __restrict__ sx, uint4* __restrict__ dx,
                          int wn8, int xn8) {
    int i = blockIdx.x * blockDim.x + threadIdx.x;
    const float4* s;
    uint4* d;
    int j;
    if (i < wn8)                  { s = s1; d = d1; j = i; }
    else if (i < 2 * wn8)         { s = s2; d = d2; j = i - wn8; }
    else if (i < 3 * wn8)         { s = s3; d = d3; j = i - 2 * wn8; }
    else if (i < 3 * wn8 + xn8)   { s = sx; d = dx; j = i - 3 * wn8; }
    else return;
    float4 v0 = s[j * 2];       // cols 0..3
    float4 v1 = s[j * 2 + 1];   // cols 4..7
    uint4 o0, o1;
    o0.x = f2tf(v0.x); o0.y = f2tf(v1.x); o0.z = f2tf(v0.y); o0.w = f2tf(v1.y);
    o1.x = f2tf(v0.z); o1.y = f2tf(v1.z); o1.z = f2tf(v0.w); o1.w = f2tf(v1.w);
    d[j * 2]     = o0;
    d[j * 2 + 1] = o1;
}

// ---------------- kernel B: gating (one warp per token) + zero out ----------------
__global__ __launch_bounds__(256) void k_gate(const float* __restrict__ x,
                                              const float* __restrict__ gw,
                                              float4* __restrict__ out) {
    if (blockIdx.x == 0 && threadIdx.x == 0) g_readycnt = 0;

    {
        int base = blockIdx.x * 4096;
#pragma unroll
        for (int u = 0; u < 16; u++)
            out[base + threadIdx.x + 256 * u] = make_float4(0.f, 0.f, 0.f, 0.f);
    }

    int warp = (blockIdx.x * blockDim.x + threadIdx.x) >> 5;
    int lane = threadIdx.x & 31;
    if (warp >= T_TOK) return;
    const float4* xr = (const float4*)(x + (size_t)warp * HDIM);

    float acc[NEXP];
#pragma unroll
    for (int e = 0; e < NEXP; e++) acc[e] = 0.f;
    for (int h4 = lane; h4 < HDIM / 4; h4 += 32) {
        float4 xv = xr[h4];
#pragma unroll
        for (int e = 0; e < NEXP; e++) {
            float4 gv = ((const float4*)(gw + e * HDIM))[h4];
            acc[e] += xv.x * gv.x + xv.y * gv.y + xv.z * gv.z + xv.w * gv.w;
        }
    }
#pragma unroll
    for (int e = 0; e < NEXP; e++) {
#pragma unroll
        for (int off = 16; off; off >>= 1)
            acc[e] += __shfl_xor_sync(0xffffffffu, acc[e], off);
    }
    if (lane == 0) {
        float m1 = -1e30f, m2 = -1e30f;
        int i1 = 0, i2 = 0;
#pragma unroll
        for (int e = 0; e < NEXP; e++) {
            float v = acc[e];
            if (v > m1)      { m2 = m1; i2 = i1; m1 = v; i1 = e; }
            else if (v > m2) { m2 = v;  i2 = e; }
        }
        float w1v = 1.f / (1.f + expf(m2 - m1));
        g_sel[warp * 2 + 0] = i1;
        g_sel[warp * 2 + 1] = i2;
        g_rw [warp * 2 + 0] = w1v;
        g_rw [warp * 2 + 1] = 1.f - w1v;
    }
}

// ---------------- kernel C: parallel order-preserving dispatch scan ----------------
__global__ __launch_bounds__(SCAN_T) void k_scan_par() {
    __shared__ int swcnt [8][NEXP];
    __shared__ int swbase[8][NEXP];
    __shared__ int sgbase[NEXP];
    __shared__ int sagg[SCAN_B * NEXP];

    int blk = blockIdx.x, tid = threadIdx.x, w = tid >> 5, lane = tid & 31;

    const int SLICE = (NEXP * CAPP) / SCAN_B;
    for (int i = tid; i < SLICE; i += SCAN_T) {
        int idx = blk * SLICE + i;
        g_tok[idx] = 0;
        g_wgt[idx] = 0.f;
    }

    int base_i = blk * 1024 + w * 128;
    int myexp[4];
    int cnt[NEXP];
#pragma unroll
    for (int e = 0; e < NEXP; e++) cnt[e] = 0;
#pragma unroll
    for (int q = 0; q < 4; q++) {
        int i = base_i + q * 32 + lane;
        int t = i & (T_TOK - 1);
        int k = i >> LG2T;
        int e = g_sel[t * 2 + k];
        myexp[q] = e;
#pragma unroll
        for (int ee = 0; ee < NEXP; ee++) {
            unsigned m = __ballot_sync(0xffffffffu, e == ee);
            cnt[ee] += __popc(m);
        }
    }
    if (lane == 0) {
#pragma unroll
        for (int ee = 0; ee < NEXP; ee++) swcnt[w][ee] = cnt[ee];
    }
    __syncthreads();

    if (tid < NEXP) {
        int run = 0;
#pragma unroll
        for (int ww = 0; ww < 8; ww++) { swbase[ww][tid] = run; run += swcnt[ww][tid]; }
        g_agg[blk * NEXP + tid] = run;
    }
    __syncthreads();
    if (tid == 0) {
        __threadfence();
        atomicAdd(&g_readycnt, 1);
        while (atomicAdd(&g_readycnt, 0) < SCAN_B) { }
    }
    __syncthreads();

    for (int i = tid; i < SCAN_B * NEXP; i += SCAN_T) sagg[i] = __ldcg(&g_agg[i]);
    __syncthreads();

    if (tid < NEXP) {
        int b = 0;
        for (int bb = 0; bb < blk; bb++) b += sagg[bb * NEXP + tid];
        sgbase[tid] = b;
        if (blk == 0) {
            int tot = 0;
            for (int bb = 0; bb < SCAN_B; bb++) tot += sagg[bb * NEXP + tid];
            g_cnt[tid] = tot;
        }
    }
    __syncthreads();

    int run2[NEXP];
#pragma unroll
    for (int ee = 0; ee < NEXP; ee++) run2[ee] = sgbase[ee] + swbase[w][ee];
#pragma unroll
    for (int q = 0; q < 4; q++) {
        int i = base_i + q * 32 + lane;
        int t = i & (T_TOK - 1);
        int k = i >> LG2T;
        int e = myexp[q];
        int pos = 0;
        unsigned lt = (1u << lane) - 1u;
#pragma unroll
        for (int ee = 0; ee < NEXP; ee++) {
            unsigned m = __ballot_sync(0xffffffffu, e == ee);
            if (e == ee) pos = run2[ee] + __popc(m & lt);
            run2[ee] += __popc(m);
        }
        if (pos < CAP) {
            g_tok[e * CAPP + pos] = t;
            g_wgt[e * CAPP + pos] = g_rw[t * 2 + k];
        }
    }
}

// ---------------- kernel 3: GEMM1 — dual-op warp 64x32, LDS.64 fragments ----------------
// 128 thr; block 128(M) x 64(N) x {w1,w3}; stride 40 u32 per smem row (bank-conflict-free
// for uint2 fragment loads). A = g_xt (tf32 permuted), B = permuted tf32 weights.
#define F1_AST 5120            // 128*40 u32
#define F1_BST 5120            // 2*64*40
#define F1_STG (F1_AST + F1_BST)
#define F1_SMEM (2 * F1_STG * 4)

__global__ __launch_bounds__(128, 2) void k_ffn1() {
    extern __shared__ uint32_t sm[];
    __shared__ int s_tok[128];

    int e    = blockIdx.z;
    int row0 = blockIdx.x * 128;
    int n0   = blockIdx.y * 64;
    int ne   = min(g_cnt[e], CAP);
    if (row0 >= ne) return;   // ffn2 skips the same tiles
    uint32_t* hout = g_h + (size_t)e * CAPP * FDIM;

    int tid = threadIdx.x;
    s_tok[tid] = g_tok[e * CAPP + row0 + tid];
    __syncthreads();

    const uint32_t* w1e = g_w1t + (size_t)e * FDIM * HDIM;
    const uint32_t* w3e = g_w3t + (size_t)e * FDIM * HDIM;

    int a_row[8], a_c4[8];
    const uint32_t* b_src[8];
    uint32_t a_dst[8], b_dst[8];
#pragma unroll
    for (int u = 0; u < 8; u++) {
        int idx = tid + 128 * u;
        a_row[u] = idx >> 3;
        a_c4 [u] = idx & 7;
        a_dst[u] = sptr(sm + a_row[u] * 40 + a_c4[u] * 4);
        int m = idx >> 9, rem = idx & 511;
        int n = rem >> 3, c4 = rem & 7;
        b_src[u] = ((m == 0) ? w1e : w3e) + (size_t)(n0 + n) * HDIM + c4 * 4;
        b_dst[u] = sptr(sm + F1_AST + (m * 64 + n) * 40 + c4 * 4);
    }

    int warp = tid >> 5, lane = tid & 31;
    int wm = warp >> 1, wn = warp & 1;          // 2x2 warps, warp tile 64(M) x 32(N)
    int g = lane >> 2, tg = lane & 3;

    float accA[4][4][4], accB[4][4][4];
#pragma unroll
    for (int mi = 0; mi < 4; mi++)
#pragma unroll
        for (int ni = 0; ni < 4; ni++)
#pragma unroll
            for (int q = 0; q < 4; q++) { accA[mi][ni][q] = 0.f; accB[mi][ni][q] = 0.f; }

#pragma unroll
    for (int t = 0; t < 2; t++) {
        int k0 = t * 32;
        uint32_t off = t * F1_STG * 4;
#pragma unroll
        for (int u = 0; u < 8; u++) {
            CP16(a_dst[u] + off, g_xt + (size_t)s_tok[a_row[u]] * HDIM + k0 + a_c4[u] * 4);
            CP16(b_dst[u] + off, b_src[u] + k0);
        }
        CP_COMMIT();
    }

    const int NT = HDIM / 32;
#pragma unroll 1
    for (int t = 0; t < NT; t++) {
        CP_WAIT1();
        __syncthreads();
        int p = t & 1;
        const uint2* As2 = (const uint2*)(sm + p * F1_STG);
        const uint2* Bs2 = (const uint2*)(sm + p * F1_STG + F1_AST);

#pragma unroll
        for (int kk = 0; kk < 4; kk++) {
            uint32_t a[4][4];
#pragma unroll
            for (int mi = 0; mi < 4; mi++) {
                int r = wm * 64 + mi * 16;
                uint2 va = As2[(r + g)     * 20 + kk * 4 + tg];
                uint2 vb = As2[(r + 8 + g) * 20 + kk * 4 + tg];
                a[mi][0] = va.x; a[mi][1] = vb.x; a[mi][2] = va.y; a[mi][3] = vb.y;
            }
#pragma unroll
            for (int ni = 0; ni < 4; ni++) {
                int n = wn * 32 + ni * 8 + g;
                uint2 pb = Bs2[n        * 20 + kk * 4 + tg];   // w1 pair
                uint2 pc = Bs2[(64 + n) * 20 + kk * 4 + tg];   // w3 pair
#pragma unroll
                for (int mi = 0; mi < 4; mi++) {
                    mma_tf32(accA[mi][ni][0], accA[mi][ni][1], accA[mi][ni][2], accA[mi][ni][3],
                             a[mi][0], a[mi][1], a[mi][2], a[mi][3], pb.x, pb.y);
                    mma_tf32(accB[mi][ni][0], accB[mi][ni][1], accB[mi][ni][2], accB[mi][ni][3],
                             a[mi][0], a[mi][1], a[mi][2], a[mi][3], pc.x, pc.y);
                }
            }
        }
        __syncthreads();

        int tn = t + 2;
        if (tn < NT) {
            int k0 = tn * 32;
            uint32_t off = p * F1_STG * 4;
#pragma unroll
            for (int u = 0; u < 8; u++) {
                CP16(a_dst[u] + off, g_xt + (size_t)s_tok[a_row[u]] * HDIM + k0 + a_c4[u] * 4);
                CP16(b_dst[u] + off, b_src[u] + k0);
            }
        }
        CP_COMMIT();
    }

    // epilogue: h = silu(a*b), stored tf32 at PERMUTED column positions (for ffn2)
#pragma unroll
    for (int mi = 0; mi < 4; mi++) {
#pragma unroll
        for (int ni = 0; ni < 4; ni++) {
            int rbase = row0 + wm * 64 + mi * 16 + g;
            int grp = n0 + wn * 32 + ni * 8;                // 8-aligned group base
            int lc = tg * 2;                                // local col in [0,8)
#pragma unroll
            for (int h = 0; h < 2; h++) {
                int r = rbase + h * 8;
                float p0 = accA[mi][ni][h * 2 + 0] * accB[mi][ni][h * 2 + 0];
                float p1 = accA[mi][ni][h * 2 + 1] * accB[mi][ni][h * 2 + 1];
                float s0 = p0 / (1.f + expf(-p0));
                float s1 = p1 / (1.f + expf(-p1));
                hout[(size_t)r * FDIM + grp + pperm(lc)]     = f2tf(s0);
                hout[(size_t)r * FDIM + grp + pperm(lc + 1)] = f2tf(s1);
            }
        }
    }
}

// ---------------- kernel 4: GEMM2 — warp 64x64, LDS.64 fragments + weighted scatter ----------------
#define F2_AST 5120            // 128*40
#define F2_BST 5120            // 128*40
#define F2_STG (F2_AST + F2_BST)
#define F2_SMEM (2 * F2_STG * 4)

__global__ __launch_bounds__(128, 2) void k_ffn2(float* __restrict__ out) {
    extern __shared__ uint32_t sm[];
    __shared__ int   s_tok[128];
    __shared__ float s_wgt[128];

    int e    = blockIdx.z;
    int row0 = blockIdx.x * 128;
    int n0   = blockIdx.y * 128;
    int ne   = min(g_cnt[e], CAP);
    if (row0 >= ne) return;

    int tid = threadIdx.x;
    s_tok[tid] = g_tok[e * CAPP + row0 + tid];
    s_wgt[tid] = g_wgt[e * CAPP + row0 + tid];
    __syncthreads();

    const uint32_t* hin = g_h   + (size_t)e * CAPP * FDIM;
    const uint32_t* w2e = g_w2t + (size_t)e * HDIM * FDIM;

    const uint32_t* a_src[8];
    uint32_t a_dst[8];
    const uint32_t* b_src[8];
    uint32_t b_dst[8];
#pragma unroll
    for (int u = 0; u < 8; u++) {
        int idx = tid + 128 * u;
        int row = idx >> 3, c4 = idx & 7;
        a_src[u] = hin + (size_t)(row0 + row) * FDIM + c4 * 4;
        a_dst[u] = sptr(sm + row * 40 + c4 * 4);
        b_src[u] = w2e + (size_t)(n0 + row) * FDIM + c4 * 4;
        b_dst[u] = sptr(sm + F2_AST + row * 40 + c4 * 4);
    }

    int warp = tid >> 5, lane = tid & 31;
    int wm = warp >> 1, wn = warp & 1;          // warp tile 64(M) x 64(N)
    int g = lane >> 2, tg = lane & 3;

    float acc[4][8][4];
#pragma unroll
    for (int mi = 0; mi < 4; mi++)
#pragma unroll
        for (int ni = 0; ni < 8; ni++)
#pragma unroll
            for (int q = 0; q < 4; q++) acc[mi][ni][q] = 0.f;

#pragma unroll
    for (int t = 0; t < 2; t++) {
        int k0 = t * 32;
        uint32_t off = t * F2_STG * 4;
#pragma unroll
        for (int u = 0; u < 8; u++) {
            CP16(a_dst[u] + off, a_src[u] + k0);
            CP16(b_dst[u] + off, b_src[u] + k0);
        }
        CP_COMMIT();
    }

    const int NT = FDIM / 32;
#pragma unroll 1
    for (int t = 0; t < NT; t++) {
        CP_WAIT1();
        __syncthreads();
        int p = t & 1;
        const uint2* As2 = (const uint2*)(sm + p * F2_STG);
        const uint2* Bs2 = (const uint2*)(sm + p * F2_STG + F2_AST);

#pragma unroll
        for (int kk = 0; kk < 4; kk++) {
            uint32_t a[4][4];
#pragma unroll
            for (int mi = 0; mi < 4; mi++) {
                int r = wm * 64 + mi * 16;
                uint2 va = As2[(r + g)     * 20 + kk * 4 + tg];
                uint2 vb = As2[(r + 8 + g) * 20 + kk * 4 + tg];
                a[mi][0] = va.x; a[mi][1] = vb.x; a[mi][2] = va.y; a[mi][3] = vb.y;
            }
#pragma unroll
            for (int ni = 0; ni < 8; ni++) {
                int n = wn * 64 + ni * 8 + g;
                uint2 pb = Bs2[n * 20 + kk * 4 + tg];
#pragma unroll
                for (int mi = 0; mi < 4; mi++)
                    mma_tf32(acc[mi][ni][0], acc[mi][ni][1], acc[mi][ni][2], acc[mi][ni][3],
                             a[mi][0], a[mi][1], a[mi][2], a[mi][3], pb.x, pb.y);
            }
        }
        __syncthreads();

        int tn = t + 2;
        if (tn < NT) {
            int k0 = tn * 32;
            uint32_t off = p * F2_STG * 4;
#pragma unroll
            for (int u = 0; u < 8; u++) {
                CP16(a_dst[u] + off, a_src[u] + k0);
                CP16(b_dst[u] + off, b_src[u] + k0);
            }
        }
        CP_COMMIT();
    }

    // epilogue: weighted atomic scatter (output columns unpermuted)
#pragma unroll
    for (int mi = 0; mi < 4; mi++) {
#pragma unroll
        for (int ni = 0; ni < 8; ni++) {
            int cbase = n0 + wn * 64 + ni * 8 + tg * 2;
#pragma unroll
            for (int hh = 0; hh < 2; hh++) {
                int rl = wm * 64 + mi * 16 + g + hh * 8;
                float w = s_wgt[rl];
                if (w != 0.f) {
                    int tok = s_tok[rl];
                    atomicAdd(&out[(size_t)tok * HDIM + cbase],     acc[mi][ni][hh * 2 + 0] * w);
                    atomicAdd(&out[(size_t)tok * HDIM + cbase + 1], acc[mi][ni][hh * 2 + 1] * w);
                }
            }
        }
    }
}

// ---------------- launch ----------------
extern "C" void kernel_launch(void* const* d_in, const int* in_sizes, int n_in,
                              void* d_out, int out_size) {
    const float* x  = nullptr;
    const float* gw = nullptr;
    const float* wbig[3] = {nullptr, nullptr, nullptr};
    int nbig = 0;
    for (int i = 0; i < n_in; i++) {
        long long sz = in_sizes[i];
        if (sz == (long long)T_TOK * HDIM)      x = (const float*)d_in[i];
        else if (sz == (long long)NEXP * HDIM)  gw = (const float*)d_in[i];
        else if (nbig < 3)                      wbig[nbig++] = (const float*)d_in[i];
    }
    const float* w1 = wbig[0];
    const float* w2 = wbig[1];
    const float* w3 = wbig[2];
    float* out = (float*)d_out;

    cudaFuncSetAttribute(k_ffn1, cudaFuncAttributeMaxDynamicSharedMemorySize, F1_SMEM);
    cudaFuncSetAttribute(k_ffn2, cudaFuncAttributeMaxDynamicSharedMemorySize, F2_SMEM);

    uint32_t* w1t; cudaGetSymbolAddress((void**)&w1t, g_w1t);
    uint32_t* w2t; cudaGetSymbolAddress((void**)&w2t, g_w2t);
    uint32_t* w3t; cudaGetSymbolAddress((void**)&w3t, g_w3t);
    uint32_t* xt;  cudaGetSymbolAddress((void**)&xt,  g_xt);

    int wn8 = NEXP * FDIM * HDIM / 8;
    int xn8 = T_TOK * HDIM / 8;

    // launch index 3 (k_ffn1) is the one ncu captures
    k_cvt_all<<<(3 * wn8 + xn8 + 255) / 256, 256>>>(
        (const float4*)w1, (uint4*)w1t,
        (const float4*)w2, (uint4*)w2t,
        (const float4*)w3, (uint4*)w3t,
        (const float4*)x,  (uint4*)xt, wn8, xn8);                               // 0
    k_gate<<<T_TOK / 8, 256>>>(x, gw, (float4*)out);                            // 1
    k_scan_par<<<SCAN_B, SCAN_T>>>();                                           // 2
    k_ffn1<<<dim3(CAPP / 128, FDIM / 64, NEXP), 128, F1_SMEM>>>();              // 3 <- profiled
    k_ffn2<<<dim3(CAPP / 128, HDIM / 128, NEXP), 128, F2_SMEM>>>(out);          // 4
}

// round 14
// speedup vs baseline: 1.1888x; 1.1888x over previous
#include <cuda_runtime.h>
#include <cuda_bf16.h>
#include <cstdint>
#include <math.h>

#define T_TOK 16384
#define HDIM  2048
#define FDIM  256
#define NEXP  12
#define CAP   1707
#define CAPP  1792   // 14 * 128
#define LG2T  14
#define SCAN_B 32
#define SCAN_T 256

// ---------------- scratch (device globals; no allocs allowed) ----------------
__device__ float g_rw [T_TOK * 2];
__device__ int   g_sel[T_TOK * 2];
__device__ int   g_tok[NEXP * CAPP];
__device__ float g_wgt[NEXP * CAPP];
__device__ int   g_cnt[NEXP];
__device__ int   g_agg[SCAN_B * NEXP];
__device__ int   g_readycnt;
__device__ __align__(16) uint32_t g_xt [T_TOK * HDIM];            // tf32 x (written by gate)
__device__ __align__(16) uint32_t g_h  [NEXP * CAPP * FDIM];      // tf32 intermediate
__device__ __align__(16) uint32_t g_w1t[NEXP * FDIM * HDIM];      // tf32 weights
__device__ __align__(16) uint32_t g_w2t[NEXP * HDIM * FDIM];
__device__ __align__(16) uint32_t g_w3t[NEXP * FDIM * HDIM];

// ---------------- helpers ----------------
__device__ __forceinline__ uint32_t f2tf(float f) {
    uint32_t u;
    asm("cvt.rna.tf32.f32 %0, %1;" : "=r"(u) : "f"(f));
    return u;
}

__device__ __forceinline__ void mma_tf32(float& d0, float& d1, float& d2, float& d3,
                                         uint32_t a0, uint32_t a1, uint32_t a2, uint32_t a3,
                                         uint32_t b0, uint32_t b1) {
    asm volatile(
        "mma.sync.aligned.m16n8k8.row.col.f32.tf32.tf32.f32 "
        "{%0,%1,%2,%3}, {%4,%5,%6,%7}, {%8,%9}, {%0,%1,%2,%3};"
        : "+f"(d0), "+f"(d1), "+f"(d2), "+f"(d3)
        : "r"(a0), "r"(a1), "r"(a2), "r"(a3), "r"(b0), "r"(b1));
}

__device__ __forceinline__ uint32_t sptr(const void* p) {
    return (uint32_t)__cvta_generic_to_shared(p);
}

#define CP16(dst_u32, src_ptr) \
    asm volatile("cp.async.cg.shared.global [%0], [%1], 16;" :: "r"(dst_u32), "l"(src_ptr))
#define CP_COMMIT() asm volatile("cp.async.commit_group;")
#define CP_WAIT1()  asm volatile("cp.async.wait_group 1;")

// ---------------- kernel A: convert w1/w2/w3 fp32 -> tf32 ----------------
__global__ void k_cvt_all(const float4* __restrict__ s1, uint4* __restrict__ d1,
                          const float4* __restrict__ s2, uint4* __restrict__ d2,
                          const float4* __restrict__ s3, uint4* __restrict__ d3, int wn4) {
    int i = blockIdx.x * blockDim.x + threadIdx.x;
    const float4* s;
    uint4* d;
    int j;
    if (i < wn4)              { s = s1; d = d1; j = i; }
    else if (i < 2 * wn4)     { s = s2; d = d2; j = i - wn4; }
    else if (i < 3 * wn4)     { s = s3; d = d3; j = i - 2 * wn4; }
    else return;
    float4 v = s[j];
    uint4 u;
    u.x = f2tf(v.x); u.y = f2tf(v.y); u.z = f2tf(v.z); u.w = f2tf(v.w);
    d[j] = u;
}

// ---------------- kernel B: gating + zero out + x->tf32 conversion ----------------
__global__ __launch_bounds__(256) void k_gate(const float* __restrict__ x,
                                              const float* __restrict__ gw,
                                              float4* __restrict__ out) {
    if (blockIdx.x == 0 && threadIdx.x == 0) g_readycnt = 0;

    // zero this block's 8 token rows of out
    {
        int base = blockIdx.x * 4096;
#pragma unroll
        for (int u = 0; u < 16; u++)
            out[base + threadIdx.x + 256 * u] = make_float4(0.f, 0.f, 0.f, 0.f);
    }

    int warp = (blockIdx.x * blockDim.x + threadIdx.x) >> 5;
    int lane = threadIdx.x & 31;
    if (warp >= T_TOK) return;
    const float4* xr = (const float4*)(x + (size_t)warp * HDIM);
    uint4* xo = (uint4*)(g_xt + (size_t)warp * HDIM);

    float acc[NEXP];
#pragma unroll
    for (int e = 0; e < NEXP; e++) acc[e] = 0.f;
    for (int h4 = lane; h4 < HDIM / 4; h4 += 32) {
        float4 xv = xr[h4];
        uint4 u;
        u.x = f2tf(xv.x); u.y = f2tf(xv.y); u.z = f2tf(xv.z); u.w = f2tf(xv.w);
        xo[h4] = u;
#pragma unroll
        for (int e = 0; e < NEXP; e++) {
            float4 gv = ((const float4*)(gw + e * HDIM))[h4];
            acc[e] += xv.x * gv.x + xv.y * gv.y + xv.z * gv.z + xv.w * gv.w;
        }
    }
#pragma unroll
    for (int e = 0; e < NEXP; e++) {
#pragma unroll
        for (int off = 16; off; off >>= 1)
            acc[e] += __shfl_xor_sync(0xffffffffu, acc[e], off);
    }
    if (lane == 0) {
        float m1 = -1e30f, m2 = -1e30f;
        int i1 = 0, i2 = 0;
#pragma unroll
        for (int e = 0; e < NEXP; e++) {
            float v = acc[e];
            if (v > m1)      { m2 = m1; i2 = i1; m1 = v; i1 = e; }
            else if (v > m2) { m2 = v;  i2 = e; }
        }
        float w1v = 1.f / (1.f + expf(m2 - m1));
        g_sel[warp * 2 + 0] = i1;
        g_sel[warp * 2 + 1] = i2;
        g_rw [warp * 2 + 0] = w1v;
        g_rw [warp * 2 + 1] = 1.f - w1v;
    }
}

// ---------------- kernel C: parallel order-preserving dispatch scan ----------------
__global__ __launch_bounds__(SCAN_T) void k_scan_par() {
    __shared__ int swcnt [8][NEXP];
    __shared__ int swbase[8][NEXP];
    __shared__ int sgbase[NEXP];
    __shared__ int sagg[SCAN_B * NEXP];

    int blk = blockIdx.x, tid = threadIdx.x, w = tid >> 5, lane = tid & 31;

    const int SLICE = (NEXP * CAPP) / SCAN_B;   // 672
    for (int i = tid; i < SLICE; i += SCAN_T) {
        int idx = blk * SLICE + i;
        g_tok[idx] = 0;
        g_wgt[idx] = 0.f;
    }

    int base_i = blk * 1024 + w * 128;
    int myexp[4];
    int cnt[NEXP];
#pragma unroll
    for (int e = 0; e < NEXP; e++) cnt[e] = 0;
#pragma unroll
    for (int q = 0; q < 4; q++) {
        int i = base_i + q * 32 + lane;
        int t = i & (T_TOK - 1);
        int k = i >> LG2T;
        int e = g_sel[t * 2 + k];
        myexp[q] = e;
#pragma unroll
        for (int ee = 0; ee < NEXP; ee++) {
            unsigned m = __ballot_sync(0xffffffffu, e == ee);
            cnt[ee] += __popc(m);
        }
    }
    if (lane == 0) {
#pragma unroll
        for (int ee = 0; ee < NEXP; ee++) swcnt[w][ee] = cnt[ee];
    }
    __syncthreads();

    if (tid < NEXP) {
        int run = 0;
#pragma unroll
        for (int ww = 0; ww < 8; ww++) { swbase[ww][tid] = run; run += swcnt[ww][tid]; }
        g_agg[blk * NEXP + tid] = run;
    }
    __syncthreads();
    if (tid == 0) {
        __threadfence();
        atomicAdd(&g_readycnt, 1);
        while (atomicAdd(&g_readycnt, 0) < SCAN_B) { }
    }
    __syncthreads();

    for (int i = tid; i < SCAN_B * NEXP; i += SCAN_T) sagg[i] = __ldcg(&g_agg[i]);
    __syncthreads();

    if (tid < NEXP) {
        int b = 0;
        for (int bb = 0; bb < blk; bb++) b += sagg[bb * NEXP + tid];
        sgbase[tid] = b;
        if (blk == 0) {
            int tot = 0;
            for (int bb = 0; bb < SCAN_B; bb++) tot += sagg[bb * NEXP + tid];
            g_cnt[tid] = tot;
        }
    }
    __syncthreads();

    int run2[NEXP];
#pragma unroll
    for (int ee = 0; ee < NEXP; ee++) run2[ee] = sgbase[ee] + swbase[w][ee];
#pragma unroll
    for (int q = 0; q < 4; q++) {
        int i = base_i + q * 32 + lane;
        int t = i & (T_TOK - 1);
        int k = i >> LG2T;
        int e = myexp[q];
        int pos = 0;
        unsigned lt = (1u << lane) - 1u;
#pragma unroll
        for (int ee = 0; ee < NEXP; ee++) {
            unsigned m = __ballot_sync(0xffffffffu, e == ee);
            if (e == ee) pos = run2[ee] + __popc(m & lt);
            run2[ee] += __popc(m);
        }
        if (pos < CAP) {
            g_tok[e * CAPP + pos] = t;
            g_wgt[e * CAPP + pos] = g_rw[t * 2 + k];
        }
    }
}

// ---------------- kernel 3: GEMM1 — R9 structure, A from pre-converted g_xt ----------------
#define F1_AST 4608            // 128*36 uint32
#define F1_BST 4608            // 2*64*36
#define F1_STG (F1_AST + F1_BST)
#define F1_SMEM (2 * F1_STG * 4)

__global__ __launch_bounds__(128, 2) void k_ffn1() {
    extern __shared__ uint32_t sm[];
    __shared__ int s_tok[128];

    int e    = blockIdx.z;
    int row0 = blockIdx.x * 128;
    int n0   = blockIdx.y * 64;
    int ne   = min(g_cnt[e], CAP);
    if (row0 >= ne) return;   // ffn2 skips the same tiles
    uint32_t* hout = g_h + (size_t)e * CAPP * FDIM;

    int tid = threadIdx.x;
    s_tok[tid] = g_tok[e * CAPP + row0 + tid];
    __syncthreads();

    const uint32_t* w1e = g_w1t + (size_t)e * FDIM * HDIM;
    const uint32_t* w3e = g_w3t + (size_t)e * FDIM * HDIM;

    int a_row[8], a_c4[8];
    const uint32_t* b_src[8];
    uint32_t a_dst[8], b_dst[8];
#pragma unroll
    for (int u = 0; u < 8; u++) {
        int idx = tid + 128 * u;
        a_row[u] = idx >> 3;
        a_c4 [u] = idx & 7;
        a_dst[u] = sptr(sm + a_row[u] * 36 + a_c4[u] * 4);
        int m = idx >> 9, rem = idx & 511;     // m: 0 = w1, 1 = w3
        int n = rem >> 3, c4 = rem & 7;
        b_src[u] = ((m == 0) ? w1e : w3e) + (size_t)(n0 + n) * HDIM + c4 * 4;
        b_dst[u] = sptr(sm + F1_AST + (m * 64 + n) * 36 + c4 * 4);
    }

    int warp = tid >> 5, lane = tid & 31;
    int wm = warp >> 1, wn = warp & 1;          // 2x2 warps, warp tile 64(M) x 32(N)
    int g = lane >> 2, tg = lane & 3;

    float accA[4][4][4], accB[4][4][4];
#pragma unroll
    for (int mi = 0; mi < 4; mi++)
#pragma unroll
        for (int ni = 0; ni < 4; ni++)
#pragma unroll
            for (int q = 0; q < 4; q++) { accA[mi][ni][q] = 0.f; accB[mi][ni][q] = 0.f; }

#pragma unroll
    for (int t = 0; t < 2; t++) {
        int k0 = t * 32;
        uint32_t off = t * F1_STG * 4;
#pragma unroll
        for (int u = 0; u < 8; u++) {
            CP16(a_dst[u] + off, g_xt + (size_t)s_tok[a_row[u]] * HDIM + k0 + a_c4[u] * 4);
            CP16(b_dst[u] + off, b_src[u] + k0);
        }
        CP_COMMIT();
    }

    const int NT = HDIM / 32;
#pragma unroll 1
    for (int t = 0; t < NT; t++) {
        CP_WAIT1();
        __syncthreads();
        int p = t & 1;
        const uint32_t* As = sm + p * F1_STG;
        const uint32_t* Bs = As + F1_AST;

#pragma unroll
        for (int kk = 0; kk < 4; kk++) {
            uint32_t a[4][4];
#pragma unroll
            for (int mi = 0; mi < 4; mi++) {
                int r = wm * 64 + mi * 16;
                a[mi][0] = As[(r + g)     * 36 + kk * 8 + tg];
                a[mi][1] = As[(r + 8 + g) * 36 + kk * 8 + tg];
                a[mi][2] = As[(r + g)     * 36 + kk * 8 + tg + 4];
                a[mi][3] = As[(r + 8 + g) * 36 + kk * 8 + tg + 4];
            }
#pragma unroll
            for (int ni = 0; ni < 4; ni++) {
                int n = wn * 32 + ni * 8 + g;
                uint32_t b0 = Bs[n * 36 + kk * 8 + tg];
                uint32_t b1 = Bs[n * 36 + kk * 8 + tg + 4];
                uint32_t c0 = Bs[(64 + n) * 36 + kk * 8 + tg];
                uint32_t c1 = Bs[(64 + n) * 36 + kk * 8 + tg + 4];
#pragma unroll
                for (int mi = 0; mi < 4; mi++) {
                    mma_tf32(accA[mi][ni][0], accA[mi][ni][1], accA[mi][ni][2], accA[mi][ni][3],
                             a[mi][0], a[mi][1], a[mi][2], a[mi][3], b0, b1);
                    mma_tf32(accB[mi][ni][0], accB[mi][ni][1], accB[mi][ni][2], accB[mi][ni][3],
                             a[mi][0], a[mi][1], a[mi][2], a[mi][3], c0, c1);
                }
            }
        }
        __syncthreads();

        int tn = t + 2;
        if (tn < NT) {
            int k0 = tn * 32;
            uint32_t off = p * F1_STG * 4;
#pragma unroll
            for (int u = 0; u < 8; u++) {
                CP16(a_dst[u] + off, g_xt + (size_t)s_tok[a_row[u]] * HDIM + k0 + a_c4[u] * 4);
                CP16(b_dst[u] + off, b_src[u] + k0);
            }
        }
        CP_COMMIT();
    }

    // epilogue: h = silu(a*b) stored as tf32
#pragma unroll
    for (int mi = 0; mi < 4; mi++) {
#pragma unroll
        for (int ni = 0; ni < 4; ni++) {
            int rbase = row0 + wm * 64 + mi * 16 + g;
            int cbase = n0 + wn * 32 + ni * 8 + tg * 2;
#pragma unroll
            for (int h = 0; h < 2; h++) {
                int r = rbase + h * 8;
                float p0 = accA[mi][ni][h * 2 + 0] * accB[mi][ni][h * 2 + 0];
                float p1 = accA[mi][ni][h * 2 + 1] * accB[mi][ni][h * 2 + 1];
                float s0 = p0 / (1.f + expf(-p0));
                float s1 = p1 / (1.f + expf(-p1));
                hout[(size_t)r * FDIM + cbase]     = f2tf(s0);
                hout[(size_t)r * FDIM + cbase + 1] = f2tf(s1);
            }
        }
    }
}

// ---------------- kernel 4: GEMM2 — R9 structure + weighted scatter ----------------
#define F2_AST 4608            // 128*36
#define F2_BST 4608            // 128*36
#define F2_STG (F2_AST + F2_BST)
#define F2_SMEM (2 * F2_STG * 4)

__global__ __launch_bounds__(128, 2) void k_ffn2(float* __restrict__ out) {
    extern __shared__ uint32_t sm[];
    __shared__ int   s_tok[128];
    __shared__ float s_wgt[128];

    int e    = blockIdx.z;
    int row0 = blockIdx.x * 128;
    int n0   = blockIdx.y * 128;
    int ne   = min(g_cnt[e], CAP);
    if (row0 >= ne) return;

    int tid = threadIdx.x;
    s_tok[tid] = g_tok[e * CAPP + row0 + tid];
    s_wgt[tid] = g_wgt[e * CAPP + row0 + tid];
    __syncthreads();

    const uint32_t* hin = g_h   + (size_t)e * CAPP * FDIM;
    const uint32_t* w2e = g_w2t + (size_t)e * HDIM * FDIM;

    const uint32_t* a_src[8];
    uint32_t a_dst[8];
    const uint32_t* b_src[8];
    uint32_t b_dst[8];
#pragma unroll
    for (int u = 0; u < 8; u++) {
        int idx = tid + 128 * u;
        int row = idx >> 3, c4 = idx & 7;
        a_src[u] = hin + (size_t)(row0 + row) * FDIM + c4 * 4;
        a_dst[u] = sptr(sm + row * 36 + c4 * 4);
        b_src[u] = w2e + (size_t)(n0 + row) * FDIM + c4 * 4;
        b_dst[u] = sptr(sm + F2_AST + row * 36 + c4 * 4);
    }

    int warp = tid >> 5, lane = tid & 31;
    int wm = warp >> 1, wn = warp & 1;          // warp tile 64(M) x 64(N)
    int g = lane >> 2, tg = lane & 3;

    float acc[4][8][4];
#pragma unroll
    for (int mi = 0; mi < 4; mi++)
#pragma unroll
        for (int ni = 0; ni < 8; ni++)
#pragma unroll
            for (int q = 0; q < 4; q++) acc[mi][ni][q] = 0.f;

#pragma unroll
    for (int t = 0; t < 2; t++) {
        int k0 = t * 32;
        uint32_t off = t * F2_STG * 4;
#pragma unroll
        for (int u = 0; u < 8; u++) {
            CP16(a_dst[u] + off, a_src[u] + k0);
            CP16(b_dst[u] + off, b_src[u] + k0);
        }
        CP_COMMIT();
    }

    const int NT = FDIM / 32;
#pragma unroll 1
    for (int t = 0; t < NT; t++) {
        CP_WAIT1();
        __syncthreads();
        int p = t & 1;
        const uint32_t* As = sm + p * F2_STG;
        const uint32_t* Bs = As + F2_AST;

#pragma unroll
        for (int kk = 0; kk < 4; kk++) {
            uint32_t a[4][4];
#pragma unroll
            for (int mi = 0; mi < 4; mi++) {
                int r = wm * 64 + mi * 16;
                a[mi][0] = As[(r + g)     * 36 + kk * 8 + tg];
                a[mi][1] = As[(r + 8 + g) * 36 + kk * 8 + tg];
                a[mi][2] = As[(r + g)     * 36 + kk * 8 + tg + 4];
                a[mi][3] = As[(r + 8 + g) * 36 + kk * 8 + tg + 4];
            }
#pragma unroll
            for (int ni = 0; ni < 8; ni++) {
                int n = wn * 64 + ni * 8 + g;
                uint32_t b0 = Bs[n * 36 + kk * 8 + tg];
                uint32_t b1 = Bs[n * 36 + kk * 8 + tg + 4];
#pragma unroll
                for (int mi = 0; mi < 4; mi++)
                    mma_tf32(acc[mi][ni][0], acc[mi][ni][1], acc[mi][ni][2], acc[mi][ni][3],
                             a[mi][0], a[mi][1], a[mi][2], a[mi][3], b0, b1);
            }
        }
        __syncthreads();

        int tn = t + 2;
        if (tn < NT) {
            int k0 = tn * 32;
            uint32_t off = p * F2_STG * 4;
#pragma unroll
            for (int u = 0; u < 8; u++) {
                CP16(a_dst[u] + off, a_src[u] + k0);
                CP16(b_dst[u] + off, b_src[u] + k0);
            }
        }
        CP_COMMIT();
    }

#pragma unroll
    for (int mi = 0; mi < 4; mi++) {
#pragma unroll
        for (int ni = 0; ni < 8; ni++) {
            int cbase = n0 + wn * 64 + ni * 8 + tg * 2;
#pragma unroll
            for (int hh = 0; hh < 2; hh++) {
                int rl = wm * 64 + mi * 16 + g + hh * 8;
                float w = s_wgt[rl];
                if (w != 0.f) {
                    int tok = s_tok[rl];
                    atomicAdd(&out[(size_t)tok * HDIM + cbase],     acc[mi][ni][hh * 2 + 0] * w);
                    atomicAdd(&out[(size_t)tok * HDIM + cbase + 1], acc[mi][ni][hh * 2 + 1] * w);
                }
            }
        }
    }
}

// ---------------- launch ----------------
extern "C" void kernel_launch(void* const* d_in, const int* in_sizes, int n_in,
                              void* d_out, int out_size) {
    const float* x  = nullptr;
    const float* gw = nullptr;
    const float* wbig[3] = {nullptr, nullptr, nullptr};
    int nbig = 0;
    for (int i = 0; i < n_in; i++) {
        long long sz = in_sizes[i];
        if (sz == (long long)T_TOK * HDIM)      x = (const float*)d_in[i];
        else if (sz == (long long)NEXP * HDIM)  gw = (const float*)d_in[i];
        else if (nbig < 3)                      wbig[nbig++] = (const float*)d_in[i];
    }
    const float* w1 = wbig[0];
    const float* w2 = wbig[1];
    const float* w3 = wbig[2];
    float* out = (float*)d_out;

    cudaFuncSetAttribute(k_ffn1, cudaFuncAttributeMaxDynamicSharedMemorySize, F1_SMEM);
    cudaFuncSetAttribute(k_ffn2, cudaFuncAttributeMaxDynamicSharedMemorySize, F2_SMEM);

    uint32_t* w1t; cudaGetSymbolAddress((void**)&w1t, g_w1t);
    uint32_t* w2t; cudaGetSymbolAddress((void**)&w2t, g_w2t);
    uint32_t* w3t; cudaGetSymbolAddress((void**)&w3t, g_w3t);

    int wn4 = NEXP * FDIM * HDIM / 4;

    // launch index 3 (k_ffn1) is the one ncu captures
    k_cvt_all<<<(3 * wn4 + 255) / 256, 256>>>(
        (const float4*)w1, (uint4*)w1t,
        (const float4*)w2, (uint4*)w2t,
        (const float4*)w3, (uint4*)w3t, wn4);                                   // 0
    k_gate<<<T_TOK / 8, 256>>>(x, gw, (float4*)out);                            // 1
    k_scan_par<<<SCAN_B, SCAN_T>>>();                                           // 2
    k_ffn1<<<dim3(CAPP / 128, FDIM / 64, NEXP), 128, F1_SMEM>>>();              // 3 <- profiled
    k_ffn2<<<dim3(CAPP / 128, HDIM / 128, NEXP), 128, F2_SMEM>>>(out);          // 4
}

// round 16
// speedup vs baseline: 1.2604x; 1.0603x over previous
#include <cuda_runtime.h>
#include <cuda_bf16.h>
#include <cstdint>
#include <math.h>

#define T_TOK 16384
#define HDIM  2048
#define FDIM  256
#define NEXP  12
#define CAP   1707
#define CAPP  1792   // 14 * 128
#define LG2T  14
#define SCAN_B 32
#define SCAN_T 256

// ---------------- scratch (device globals; no allocs allowed) ----------------
__device__ float g_rw [T_TOK * 2];
__device__ int   g_sel[T_TOK * 2];
__device__ int   g_tok[NEXP * CAPP];
__device__ float g_wgt[NEXP * CAPP];
__device__ int   g_cnt[NEXP];
__device__ int   g_agg[SCAN_B * NEXP];
__device__ int   g_readycnt;
__device__ __align__(16) uint32_t g_xt [T_TOK * HDIM];            // tf32 x (written by gate)
__device__ __align__(16) uint32_t g_h  [NEXP * CAPP * FDIM];      // tf32 intermediate
__device__ __align__(16) uint32_t g_w1t[NEXP * FDIM * HDIM];      // tf32 weights
__device__ __align__(16) uint32_t g_w2t[NEXP * HDIM * FDIM];
__device__ __align__(16) uint32_t g_w3t[NEXP * FDIM * HDIM];

// ---------------- helpers ----------------
__device__ __forceinline__ uint32_t f2tf(float f) {
    uint32_t u;
    asm("cvt.rna.tf32.f32 %0, %1;" : "=r"(u) : "f"(f));
    return u;
}

__device__ __forceinline__ void mma_tf32(float& d0, float& d1, float& d2, float& d3,
                                         uint32_t a0, uint32_t a1, uint32_t a2, uint32_t a3,
                                         uint32_t b0, uint32_t b1) {
    asm volatile(
        "mma.sync.aligned.m16n8k8.row.col.f32.tf32.tf32.f32 "
        "{%0,%1,%2,%3}, {%4,%5,%6,%7}, {%8,%9}, {%0,%1,%2,%3};"
        : "+f"(d0), "+f"(d1), "+f"(d2), "+f"(d3)
        : "r"(a0), "r"(a1), "r"(a2), "r"(a3), "r"(b0), "r"(b1));
}

__device__ __forceinline__ void red_add_v2(float* p, float a, float b) {
    asm volatile("red.global.v2.f32.add [%0], {%1, %2};" :: "l"(p), "f"(a), "f"(b) : "memory");
}

__device__ __forceinline__ uint32_t sptr(const void* p) {
    return (uint32_t)__cvta_generic_to_shared(p);
}

#define CP16(dst_u32, src_ptr) \
    asm volatile("cp.async.cg.shared.global [%0], [%1], 16;" :: "r"(dst_u32), "l"(src_ptr))
#define CP_COMMIT() asm volatile("cp.async.commit_group;")
#define CP_WAIT1()  asm volatile("cp.async.wait_group 1;")

// ---------------- kernel A: convert w1/w2/w3 fp32 -> tf32 ----------------
__global__ void k_cvt_all(const float4* __restrict__ s1, uint4* __restrict__ d1,
                          const float4* __restrict__ s2, uint4* __restrict__ d2,
                          const float4* __restrict__ s3, uint4* __restrict__ d3, int wn4) {
    int i = blockIdx.x * blockDim.x + threadIdx.x;
    const float4* s;
    uint4* d;
    int j;
    if (i < wn4)              { s = s1; d = d1; j = i; }
    else if (i < 2 * wn4)     { s = s2; d = d2; j = i - wn4; }
    else if (i < 3 * wn4)     { s = s3; d = d3; j = i - 2 * wn4; }
    else return;
    float4 v = s[j];
    uint4 u;
    u.x = f2tf(v.x); u.y = f2tf(v.y); u.z = f2tf(v.z); u.w = f2tf(v.w);
    d[j] = u;
}

// ---------------- kernel B: gating + zero out + x->tf32 conversion ----------------
__global__ __launch_bounds__(256) void k_gate(const float* __restrict__ x,
                                              const float* __restrict__ gw,
                                              float4* __restrict__ out) {
    if (blockIdx.x == 0 && threadIdx.x == 0) g_readycnt = 0;

    // zero this block's 8 token rows of out (streaming stores — evict-first)
    {
        int base = blockIdx.x * 4096;
        float4 z = make_float4(0.f, 0.f, 0.f, 0.f);
#pragma unroll
        for (int u = 0; u < 16; u++)
            __stcs(&out[base + threadIdx.x + 256 * u], z);
    }

    int warp = (blockIdx.x * blockDim.x + threadIdx.x) >> 5;
    int lane = threadIdx.x & 31;
    if (warp >= T_TOK) return;
    const float4* xr = (const float4*)(x + (size_t)warp * HDIM);
    uint4* xo = (uint4*)(g_xt + (size_t)warp * HDIM);

    float acc[NEXP];
#pragma unroll
    for (int e = 0; e < NEXP; e++) acc[e] = 0.f;
    for (int h4 = lane; h4 < HDIM / 4; h4 += 32) {
        float4 xv = xr[h4];
        uint4 u;
        u.x = f2tf(xv.x); u.y = f2tf(xv.y); u.z = f2tf(xv.z); u.w = f2tf(xv.w);
        __stcs(&xo[h4], u);
#pragma unroll
        for (int e = 0; e < NEXP; e++) {
            float4 gv = ((const float4*)(gw + e * HDIM))[h4];
            acc[e] += xv.x * gv.x + xv.y * gv.y + xv.z * gv.z + xv.w * gv.w;
        }
    }
#pragma unroll
    for (int e = 0; e < NEXP; e++) {
#pragma unroll
        for (int off = 16; off; off >>= 1)
            acc[e] += __shfl_xor_sync(0xffffffffu, acc[e], off);
    }
    if (lane == 0) {
        float m1 = -1e30f, m2 = -1e30f;
        int i1 = 0, i2 = 0;
#pragma unroll
        for (int e = 0; e < NEXP; e++) {
            float v = acc[e];
            if (v > m1)      { m2 = m1; i2 = i1; m1 = v; i1 = e; }
            else if (v > m2) { m2 = v;  i2 = e; }
        }
        float w1v = 1.f / (1.f + expf(m2 - m1));
        g_sel[warp * 2 + 0] = i1;
        g_sel[warp * 2 + 1] = i2;
        g_rw [warp * 2 + 0] = w1v;
        g_rw [warp * 2 + 1] = 1.f - w1v;
    }
}

// ---------------- kernel C: parallel order-preserving dispatch scan ----------------
__global__ __launch_bounds__(SCAN_T) void k_scan_par() {
    __shared__ int swcnt [8][NEXP];
    __shared__ int swbase[8][NEXP];
    __shared__ int sgbase[NEXP];
    __shared__ int sagg[SCAN_B * NEXP];

    int blk = blockIdx.x, tid = threadIdx.x, w = tid >> 5, lane = tid & 31;

    const int SLICE = (NEXP * CAPP) / SCAN_B;   // 672
    for (int i = tid; i < SLICE; i += SCAN_T) {
        int idx = blk * SLICE + i;
        g_tok[idx] = 0;
        g_wgt[idx] = 0.f;
    }

    int base_i = blk * 1024 + w * 128;
    int myexp[4];
    int cnt[NEXP];
#pragma unroll
    for (int e = 0; e < NEXP; e++) cnt[e] = 0;
#pragma unroll
    for (int q = 0; q < 4; q++) {
        int i = base_i + q * 32 + lane;
        int t = i & (T_TOK - 1);
        int k = i >> LG2T;
        int e = g_sel[t * 2 + k];
        myexp[q] = e;
#pragma unroll
        for (int ee = 0; ee < NEXP; ee++) {
            unsigned m = __ballot_sync(0xffffffffu, e == ee);
            cnt[ee] += __popc(m);
        }
    }
    if (lane == 0) {
#pragma unroll
        for (int ee = 0; ee < NEXP; ee++) swcnt[w][ee] = cnt[ee];
    }
    __syncthreads();

    if (tid < NEXP) {
        int run = 0;
#pragma unroll
        for (int ww = 0; ww < 8; ww++) { swbase[ww][tid] = run; run += swcnt[ww][tid]; }
        g_agg[blk * NEXP + tid] = run;
    }
    __syncthreads();
    if (tid == 0) {
        __threadfence();
        atomicAdd(&g_readycnt, 1);
        while (atomicAdd(&g_readycnt, 0) < SCAN_B) { }
    }
    __syncthreads();

    for (int i = tid; i < SCAN_B * NEXP; i += SCAN_T) sagg[i] = __ldcg(&g_agg[i]);
    __syncthreads();

    if (tid < NEXP) {
        int b = 0;
        for (int bb = 0; bb < blk; bb++) b += sagg[bb * NEXP + tid];
        sgbase[tid] = b;
        if (blk == 0) {
            int tot = 0;
            for (int bb = 0; bb < SCAN_B; bb++) tot += sagg[bb * NEXP + tid];
            g_cnt[tid] = tot;
        }
    }
    __syncthreads();

    int run2[NEXP];
#pragma unroll
    for (int ee = 0; ee < NEXP; ee++) run2[ee] = sgbase[ee] + swbase[w][ee];
#pragma unroll
    for (int q = 0; q < 4; q++) {
        int i = base_i + q * 32 + lane;
        int t = i & (T_TOK - 1);
        int k = i >> LG2T;
        int e = myexp[q];
        int pos = 0;
        unsigned lt = (1u << lane) - 1u;
#pragma unroll
        for (int ee = 0; ee < NEXP; ee++) {
            unsigned m = __ballot_sync(0xffffffffu, e == ee);
            if (e == ee) pos = run2[ee] + __popc(m & lt);
            run2[ee] += __popc(m);
        }
        if (pos < CAP) {
            g_tok[e * CAPP + pos] = t;
            g_wgt[e * CAPP + pos] = g_rw[t * 2 + k];
        }
    }
}

// ---------------- kernel 3: GEMM1 — R14 structure (frozen) ----------------
#define F1_AST 4608            // 128*36 uint32
#define F1_BST 4608            // 2*64*36
#define F1_STG (F1_AST + F1_BST)
#define F1_SMEM (2 * F1_STG * 4)

__global__ __launch_bounds__(128, 2) void k_ffn1() {
    extern __shared__ uint32_t sm[];
    __shared__ int s_tok[128];

    int e    = blockIdx.z;
    int row0 = blockIdx.x * 128;
    int n0   = blockIdx.y * 64;
    int ne   = min(g_cnt[e], CAP);
    if (row0 >= ne) return;   // ffn2 skips the same tiles
    uint32_t* hout = g_h + (size_t)e * CAPP * FDIM;

    int tid = threadIdx.x;
    s_tok[tid] = g_tok[e * CAPP + row0 + tid];
    __syncthreads();

    const uint32_t* w1e = g_w1t + (size_t)e * FDIM * HDIM;
    const uint32_t* w3e = g_w3t + (size_t)e * FDIM * HDIM;

    int a_row[8], a_c4[8];
    const uint32_t* b_src[8];
    uint32_t a_dst[8], b_dst[8];
#pragma unroll
    for (int u = 0; u < 8; u++) {
        int idx = tid + 128 * u;
        a_row[u] = idx >> 3;
        a_c4 [u] = idx & 7;
        a_dst[u] = sptr(sm + a_row[u] * 36 + a_c4[u] * 4);
        int m = idx >> 9, rem = idx & 511;     // m: 0 = w1, 1 = w3
        int n = rem >> 3, c4 = rem & 7;
        b_src[u] = ((m == 0) ? w1e : w3e) + (size_t)(n0 + n) * HDIM + c4 * 4;
        b_dst[u] = sptr(sm + F1_AST + (m * 64 + n) * 36 + c4 * 4);
    }

    int warp = tid >> 5, lane = tid & 31;
    int wm = warp >> 1, wn = warp & 1;          // 2x2 warps, warp tile 64(M) x 32(N)
    int g = lane >> 2, tg = lane & 3;

    float accA[4][4][4], accB[4][4][4];
#pragma unroll
    for (int mi = 0; mi < 4; mi++)
#pragma unroll
        for (int ni = 0; ni < 4; ni++)
#pragma unroll
            for (int q = 0; q < 4; q++) { accA[mi][ni][q] = 0.f; accB[mi][ni][q] = 0.f; }

#pragma unroll
    for (int t = 0; t < 2; t++) {
        int k0 = t * 32;
        uint32_t off = t * F1_STG * 4;
#pragma unroll
        for (int u = 0; u < 8; u++) {
            CP16(a_dst[u] + off, g_xt + (size_t)s_tok[a_row[u]] * HDIM + k0 + a_c4[u] * 4);
            CP16(b_dst[u] + off, b_src[u] + k0);
        }
        CP_COMMIT();
    }

    const int NT = HDIM / 32;
#pragma unroll 1
    for (int t = 0; t < NT; t++) {
        CP_WAIT1();
        __syncthreads();
        int p = t & 1;
        const uint32_t* As = sm + p * F1_STG;
        const uint32_t* Bs = As + F1_AST;

#pragma unroll
        for (int kk = 0; kk < 4; kk++) {
            uint32_t a[4][4];
#pragma unroll
            for (int mi = 0; mi < 4; mi++) {
                int r = wm * 64 + mi * 16;
                a[mi][0] = As[(r + g)     * 36 + kk * 8 + tg];
                a[mi][1] = As[(r + 8 + g) * 36 + kk * 8 + tg];
                a[mi][2] = As[(r + g)     * 36 + kk * 8 + tg + 4];
                a[mi][3] = As[(r + 8 + g) * 36 + kk * 8 + tg + 4];
            }
#pragma unroll
            for (int ni = 0; ni < 4; ni++) {
                int n = wn * 32 + ni * 8 + g;
                uint32_t b0 = Bs[n * 36 + kk * 8 + tg];
                uint32_t b1 = Bs[n * 36 + kk * 8 + tg + 4];
                uint32_t c0 = Bs[(64 + n) * 36 + kk * 8 + tg];
                uint32_t c1 = Bs[(64 + n) * 36 + kk * 8 + tg + 4];
#pragma unroll
                for (int mi = 0; mi < 4; mi++) {
                    mma_tf32(accA[mi][ni][0], accA[mi][ni][1], accA[mi][ni][2], accA[mi][ni][3],
                             a[mi][0], a[mi][1], a[mi][2], a[mi][3], b0, b1);
                    mma_tf32(accB[mi][ni][0], accB[mi][ni][1], accB[mi][ni][2], accB[mi][ni][3],
                             a[mi][0], a[mi][1], a[mi][2], a[mi][3], c0, c1);
                }
            }
        }
        __syncthreads();

        int tn = t + 2;
        if (tn < NT) {
            int k0 = tn * 32;
            uint32_t off = p * F1_STG * 4;
#pragma unroll
            for (int u = 0; u < 8; u++) {
                CP16(a_dst[u] + off, g_xt + (size_t)s_tok[a_row[u]] * HDIM + k0 + a_c4[u] * 4);
                CP16(b_dst[u] + off, b_src[u] + k0);
            }
        }
        CP_COMMIT();
    }

    // epilogue: h = silu(a*b) stored as tf32
#pragma unroll
    for (int mi = 0; mi < 4; mi++) {
#pragma unroll
        for (int ni = 0; ni < 4; ni++) {
            int rbase = row0 + wm * 64 + mi * 16 + g;
            int cbase = n0 + wn * 32 + ni * 8 + tg * 2;
#pragma unroll
            for (int h = 0; h < 2; h++) {
                int r = rbase + h * 8;
                float p0 = accA[mi][ni][h * 2 + 0] * accB[mi][ni][h * 2 + 0];
                float p1 = accA[mi][ni][h * 2 + 1] * accB[mi][ni][h * 2 + 1];
                float s0 = p0 / (1.f + expf(-p0));
                float s1 = p1 / (1.f + expf(-p1));
                hout[(size_t)r * FDIM + cbase]     = f2tf(s0);
                hout[(size_t)r * FDIM + cbase + 1] = f2tf(s1);
            }
        }
    }
}

// ---------------- kernel 4: GEMM2 — R14 structure + red.v2 weighted scatter ----------------
#define F2_AST 4608            // 128*36
#define F2_BST 4608            // 128*36
#define F2_STG (F2_AST + F2_BST)
#define F2_SMEM (2 * F2_STG * 4)

__global__ __launch_bounds__(128, 2) void k_ffn2(float* __restrict__ out) {
    extern __shared__ uint32_t sm[];
    __shared__ int   s_tok[128];
    __shared__ float s_wgt[128];

    int e    = blockIdx.z;
    int row0 = blockIdx.x * 128;
    int n0   = blockIdx.y * 128;
    int ne   = min(g_cnt[e], CAP);
    if (row0 >= ne) return;

    int tid = threadIdx.x;
    s_tok[tid] = g_tok[e * CAPP + row0 + tid];
    s_wgt[tid] = g_wgt[e * CAPP + row0 + tid];
    __syncthreads();

    const uint32_t* hin = g_h   + (size_t)e * CAPP * FDIM;
    const uint32_t* w2e = g_w2t + (size_t)e * HDIM * FDIM;

    const uint32_t* a_src[8];
    uint32_t a_dst[8];
    const uint32_t* b_src[8];
    uint32_t b_dst[8];
#pragma unroll
    for (int u = 0; u < 8; u++) {
        int idx = tid + 128 * u;
        int row = idx >> 3, c4 = idx & 7;
        a_src[u] = hin + (size_t)(row0 + row) * FDIM + c4 * 4;
        a_dst[u] = sptr(sm + row * 36 + c4 * 4);
        b_src[u] = w2e + (size_t)(n0 + row) * FDIM + c4 * 4;
        b_dst[u] = sptr(sm + F2_AST + row * 36 + c4 * 4);
    }

    int warp = tid >> 5, lane = tid & 31;
    int wm = warp >> 1, wn = warp & 1;          // warp tile 64(M) x 64(N)
    int g = lane >> 2, tg = lane & 3;

    float acc[4][8][4];
#pragma unroll
    for (int mi = 0; mi < 4; mi++)
#pragma unroll
        for (int ni = 0; ni < 8; ni++)
#pragma unroll
            for (int q = 0; q < 4; q++) acc[mi][ni][q] = 0.f;

#pragma unroll
    for (int t = 0; t < 2; t++) {
        int k0 = t * 32;
        uint32_t off = t * F2_STG * 4;
#pragma unroll
        for (int u = 0; u < 8; u++) {
            CP16(a_dst[u] + off, a_src[u] + k0);
            CP16(b_dst[u] + off, b_src[u] + k0);
        }
        CP_COMMIT();
    }

    const int NT = FDIM / 32;
#pragma unroll 1
    for (int t = 0; t < NT; t++) {
        CP_WAIT1();
        __syncthreads();
        int p = t & 1;
        const uint32_t* As = sm + p * F2_STG;
        const uint32_t* Bs = As + F2_AST;

#pragma unroll
        for (int kk = 0; kk < 4; kk++) {
            uint32_t a[4][4];
#pragma unroll
            for (int mi = 0; mi < 4; mi++) {
                int r = wm * 64 + mi * 16;
                a[mi][0] = As[(r + g)     * 36 + kk * 8 + tg];
                a[mi][1] = As[(r + 8 + g) * 36 + kk * 8 + tg];
                a[mi][2] = As[(r + g)     * 36 + kk * 8 + tg + 4];
                a[mi][3] = As[(r + 8 + g) * 36 + kk * 8 + tg + 4];
            }
#pragma unroll
            for (int ni = 0; ni < 8; ni++) {
                int n = wn * 64 + ni * 8 + g;
                uint32_t b0 = Bs[n * 36 + kk * 8 + tg];
                uint32_t b1 = Bs[n * 36 + kk * 8 + tg + 4];
#pragma unroll
                for (int mi = 0; mi < 4; mi++)
                    mma_tf32(acc[mi][ni][0], acc[mi][ni][1], acc[mi][ni][2], acc[mi][ni][3],
                             a[mi][0], a[mi][1], a[mi][2], a[mi][3], b0, b1);
            }
        }
        __syncthreads();

        int tn = t + 2;
        if (tn < NT) {
            int k0 = tn * 32;
            uint32_t off = p * F2_STG * 4;
#pragma unroll
            for (int u = 0; u < 8; u++) {
                CP16(a_dst[u] + off, a_src[u] + k0);
                CP16(b_dst[u] + off, b_src[u] + k0);
            }
        }
        CP_COMMIT();
    }

    // epilogue: weighted scatter via vectorized no-return reductions
#pragma unroll
    for (int mi = 0; mi < 4; mi++) {
#pragma unroll
        for (int ni = 0; ni < 8; ni++) {
            int cbase = n0 + wn * 64 + ni * 8 + tg * 2;
#pragma unroll
            for (int hh = 0; hh < 2; hh++) {
                int rl = wm * 64 + mi * 16 + g + hh * 8;
                float w = s_wgt[rl];
                if (w != 0.f) {
                    int tok = s_tok[rl];
                    red_add_v2(&out[(size_t)tok * HDIM + cbase],
                               acc[mi][ni][hh * 2 + 0] * w,
                               acc[mi][ni][hh * 2 + 1] * w);
                }
            }
        }
    }
}

// ---------------- launch ----------------
extern "C" void kernel_launch(void* const* d_in, const int* in_sizes, int n_in,
                              void* d_out, int out_size) {
    const float* x  = nullptr;
    const float* gw = nullptr;
    const float* wbig[3] = {nullptr, nullptr, nullptr};
    int nbig = 0;
    for (int i = 0; i < n_in; i++) {
        long long sz = in_sizes[i];
        if (sz == (long long)T_TOK * HDIM)      x = (const float*)d_in[i];
        else if (sz == (long long)NEXP * HDIM)  gw = (const float*)d_in[i];
        else if (nbig < 3)                      wbig[nbig++] = (const float*)d_in[i];
    }
    const float* w1 = wbig[0];
    const float* w2 = wbig[1];
    const float* w3 = wbig[2];
    float* out = (float*)d_out;

    cudaFuncSetAttribute(k_ffn1, cudaFuncAttributeMaxDynamicSharedMemorySize, F1_SMEM);
    cudaFuncSetAttribute(k_ffn2, cudaFuncAttributeMaxDynamicSharedMemorySize, F2_SMEM);

    uint32_t* w1t; cudaGetSymbolAddress((void**)&w1t, g_w1t);
    uint32_t* w2t; cudaGetSymbolAddress((void**)&w2t, g_w2t);
    uint32_t* w3t; cudaGetSymbolAddress((void**)&w3t, g_w3t);

    int wn4 = NEXP * FDIM * HDIM / 4;

    // launch index 3 (k_ffn1) is the one ncu captures
    k_cvt_all<<<(3 * wn4 + 255) / 256, 256>>>(
        (const float4*)w1, (uint4*)w1t,
        (const float4*)w2, (uint4*)w2t,
        (const float4*)w3, (uint4*)w3t, wn4);                                   // 0
    k_gate<<<T_TOK / 8, 256>>>(x, gw, (float4*)out);                            // 1
    k_scan_par<<<SCAN_B, SCAN_T>>>();                                           // 2
    k_ffn1<<<dim3(CAPP / 128, FDIM / 64, NEXP), 128, F1_SMEM>>>();              // 3 <- profiled
    k_ffn2<<<dim3(CAPP / 128, HDIM / 128, NEXP), 128, F2_SMEM>>>(out);          // 4
}

// round 17
// speedup vs baseline: 1.8012x; 1.4290x over previous
#include <cuda_runtime.h>
#include <cuda_fp16.h>
#include <cstdint>
#include <math.h>

#define T_TOK 16384
#define HDIM  2048
#define FDIM  256
#define NEXP  12
#define CAP   1707
#define CAPP  1792   // 14 * 128
#define LG2T  14
#define SCAN_B 32
#define SCAN_T 256

// ---------------- scratch (device globals; no allocs allowed) ----------------
__device__ float g_rw [T_TOK * 2];
__device__ int   g_sel[T_TOK * 2];
__device__ int   g_tok[NEXP * CAPP];
__device__ float g_wgt[NEXP * CAPP];
__device__ int   g_cnt[NEXP];
__device__ int   g_agg[SCAN_B * NEXP];
__device__ int   g_readycnt;
__device__ __align__(16) uint32_t g_xh [T_TOK * HDIM / 2];        // fp16 x (half2 units)
__device__ __align__(16) uint32_t g_h  [NEXP * CAPP * FDIM / 2];  // fp16 intermediate
__device__ __align__(16) uint32_t g_w1t[NEXP * FDIM * HDIM / 2];  // fp16 weights
__device__ __align__(16) uint32_t g_w2t[NEXP * HDIM * FDIM / 2];
__device__ __align__(16) uint32_t g_w3t[NEXP * FDIM * HDIM / 2];

// ---------------- helpers ----------------
__device__ __forceinline__ uint32_t packh2(float a, float b) {
    __half2 h = __floats2half2_rn(a, b);   // .x = a (low) = even column
    return *(uint32_t*)&h;
}

__device__ __forceinline__ void mma_f16(float& d0, float& d1, float& d2, float& d3,
                                        uint32_t a0, uint32_t a1, uint32_t a2, uint32_t a3,
                                        uint32_t b0, uint32_t b1) {
    asm volatile(
        "mma.sync.aligned.m16n8k16.row.col.f32.f16.f16.f32 "
        "{%0,%1,%2,%3}, {%4,%5,%6,%7}, {%8,%9}, {%0,%1,%2,%3};"
        : "+f"(d0), "+f"(d1), "+f"(d2), "+f"(d3)
        : "r"(a0), "r"(a1), "r"(a2), "r"(a3), "r"(b0), "r"(b1));
}

__device__ __forceinline__ void red_add_v2(float* p, float a, float b) {
    asm volatile("red.global.v2.f32.add [%0], {%1, %2};" :: "l"(p), "f"(a), "f"(b) : "memory");
}

__device__ __forceinline__ uint32_t sptr(const void* p) {
    return (uint32_t)__cvta_generic_to_shared(p);
}

#define CP16(dst_u32, src_ptr) \
    asm volatile("cp.async.cg.shared.global [%0], [%1], 16;" :: "r"(dst_u32), "l"(src_ptr))
#define CP_COMMIT() asm volatile("cp.async.commit_group;")
#define CP_WAIT1()  asm volatile("cp.async.wait_group 1;")

// ---------------- kernel A: convert w1/w2/w3 fp32 -> fp16 ----------------
// Thread i handles 8 consecutive floats -> one uint4 (8 halves).
__global__ void k_cvt_all(const float4* __restrict__ s1, uint4* __restrict__ d1,
                          const float4* __restrict__ s2, uint4* __restrict__ d2,
                          const float4* __restrict__ s3, uint4* __restrict__ d3, int wn8) {
    int i = blockIdx.x * blockDim.x + threadIdx.x;
    const float4* s;
    uint4* d;
    int j;
    if (i < wn8)              { s = s1; d = d1; j = i; }
    else if (i < 2 * wn8)     { s = s2; d = d2; j = i - wn8; }
    else if (i < 3 * wn8)     { s = s3; d = d3; j = i - 2 * wn8; }
    else return;
    float4 v0 = s[j * 2];
    float4 v1 = s[j * 2 + 1];
    uint4 o;
    o.x = packh2(v0.x, v0.y);
    o.y = packh2(v0.z, v0.w);
    o.z = packh2(v1.x, v1.y);
    o.w = packh2(v1.z, v1.w);
    d[j] = o;
}

// ---------------- kernel B: gating + zero out + x->fp16 conversion ----------------
__global__ __launch_bounds__(256) void k_gate(const float* __restrict__ x,
                                              const float* __restrict__ gw,
                                              float4* __restrict__ out) {
    if (blockIdx.x == 0 && threadIdx.x == 0) g_readycnt = 0;

    // zero this block's 8 token rows of out (streaming stores)
    {
        int base = blockIdx.x * 4096;
        float4 z = make_float4(0.f, 0.f, 0.f, 0.f);
#pragma unroll
        for (int u = 0; u < 16; u++)
            __stcs(&out[base + threadIdx.x + 256 * u], z);
    }

    int warp = (blockIdx.x * blockDim.x + threadIdx.x) >> 5;
    int lane = threadIdx.x & 31;
    if (warp >= T_TOK) return;
    const float4* xr = (const float4*)(x + (size_t)warp * HDIM);
    uint2* xo = (uint2*)(g_xh + (size_t)warp * (HDIM / 2));

    float acc[NEXP];
#pragma unroll
    for (int e = 0; e < NEXP; e++) acc[e] = 0.f;
    for (int h4 = lane; h4 < HDIM / 4; h4 += 32) {
        float4 xv = xr[h4];
        uint2 u;
        u.x = packh2(xv.x, xv.y);
        u.y = packh2(xv.z, xv.w);
        __stcs(&xo[h4], u);
#pragma unroll
        for (int e = 0; e < NEXP; e++) {
            float4 gv = ((const float4*)(gw + e * HDIM))[h4];
            acc[e] += xv.x * gv.x + xv.y * gv.y + xv.z * gv.z + xv.w * gv.w;
        }
    }
#pragma unroll
    for (int e = 0; e < NEXP; e++) {
#pragma unroll
        for (int off = 16; off; off >>= 1)
            acc[e] += __shfl_xor_sync(0xffffffffu, acc[e], off);
    }
    if (lane == 0) {
        float m1 = -1e30f, m2 = -1e30f;
        int i1 = 0, i2 = 0;
#pragma unroll
        for (int e = 0; e < NEXP; e++) {
            float v = acc[e];
            if (v > m1)      { m2 = m1; i2 = i1; m1 = v; i1 = e; }
            else if (v > m2) { m2 = v;  i2 = e; }
        }
        float w1v = 1.f / (1.f + expf(m2 - m1));
        g_sel[warp * 2 + 0] = i1;
        g_sel[warp * 2 + 1] = i2;
        g_rw [warp * 2 + 0] = w1v;
        g_rw [warp * 2 + 1] = 1.f - w1v;
    }
}

// ---------------- kernel C: parallel order-preserving dispatch scan ----------------
__global__ __launch_bounds__(SCAN_T) void k_scan_par() {
    __shared__ int swcnt [8][NEXP];
    __shared__ int swbase[8][NEXP];
    __shared__ int sgbase[NEXP];
    __shared__ int sagg[SCAN_B * NEXP];

    int blk = blockIdx.x, tid = threadIdx.x, w = tid >> 5, lane = tid & 31;

    const int SLICE = (NEXP * CAPP) / SCAN_B;   // 672
    for (int i = tid; i < SLICE; i += SCAN_T) {
        int idx = blk * SLICE + i;
        g_tok[idx] = 0;
        g_wgt[idx] = 0.f;
    }

    int base_i = blk * 1024 + w * 128;
    int myexp[4];
    int cnt[NEXP];
#pragma unroll
    for (int e = 0; e < NEXP; e++) cnt[e] = 0;
#pragma unroll
    for (int q = 0; q < 4; q++) {
        int i = base_i + q * 32 + lane;
        int t = i & (T_TOK - 1);
        int k = i >> LG2T;
        int e = g_sel[t * 2 + k];
        myexp[q] = e;
#pragma unroll
        for (int ee = 0; ee < NEXP; ee++) {
            unsigned m = __ballot_sync(0xffffffffu, e == ee);
            cnt[ee] += __popc(m);
        }
    }
    if (lane == 0) {
#pragma unroll
        for (int ee = 0; ee < NEXP; ee++) swcnt[w][ee] = cnt[ee];
    }
    __syncthreads();

    if (tid < NEXP) {
        int run = 0;
#pragma unroll
        for (int ww = 0; ww < 8; ww++) { swbase[ww][tid] = run; run += swcnt[ww][tid]; }
        g_agg[blk * NEXP + tid] = run;
    }
    __syncthreads();
    if (tid == 0) {
        __threadfence();
        atomicAdd(&g_readycnt, 1);
        while (atomicAdd(&g_readycnt, 0) < SCAN_B) { }
    }
    __syncthreads();

    for (int i = tid; i < SCAN_B * NEXP; i += SCAN_T) sagg[i] = __ldcg(&g_agg[i]);
    __syncthreads();

    if (tid < NEXP) {
        int b = 0;
        for (int bb = 0; bb < blk; bb++) b += sagg[bb * NEXP + tid];
        sgbase[tid] = b;
        if (blk == 0) {
            int tot = 0;
            for (int bb = 0; bb < SCAN_B; bb++) tot += sagg[bb * NEXP + tid];
            g_cnt[tid] = tot;
        }
    }
    __syncthreads();

    int run2[NEXP];
#pragma unroll
    for (int ee = 0; ee < NEXP; ee++) run2[ee] = sgbase[ee] + swbase[w][ee];
#pragma unroll
    for (int q = 0; q < 4; q++) {
        int i = base_i + q * 32 + lane;
        int t = i & (T_TOK - 1);
        int k = i >> LG2T;
        int e = myexp[q];
        int pos = 0;
        unsigned lt = (1u << lane) - 1u;
#pragma unroll
        for (int ee = 0; ee < NEXP; ee++) {
            unsigned m = __ballot_sync(0xffffffffu, e == ee);
            if (e == ee) pos = run2[ee] + __popc(m & lt);
            run2[ee] += __popc(m);
        }
        if (pos < CAP) {
            g_tok[e * CAPP + pos] = t;
            g_wgt[e * CAPP + pos] = g_rw[t * 2 + k];
        }
    }
}

// ---------------- kernel 3: GEMM1 fp16 — dual-op warp 64x32, m16n8k16 ----------------
// Block 128(M) x 64(N) x {w1,w3}. K-tile = 32 halves (64B/row = 4x16B chunks).
// smem row stride = 20 u32 (conflict-free for the 8x4 fragment lane pattern).
#define F1_AST 2560            // 128*20 u32
#define F1_BST 2560            // 2*64*20
#define F1_STG (F1_AST + F1_BST)
#define F1_SMEM (2 * F1_STG * 4)

__global__ __launch_bounds__(128, 2) void k_ffn1() {
    extern __shared__ uint32_t sm[];
    __shared__ int s_tok[128];

    int e    = blockIdx.z;
    int row0 = blockIdx.x * 128;
    int n0   = blockIdx.y * 64;
    int ne   = min(g_cnt[e], CAP);
    if (row0 >= ne) return;   // ffn2 skips the same tiles
    uint32_t* hout = g_h + (size_t)e * CAPP * (FDIM / 2);

    int tid = threadIdx.x;
    s_tok[tid] = g_tok[e * CAPP + row0 + tid];
    __syncthreads();

    const uint32_t* w1e = g_w1t + (size_t)e * FDIM * (HDIM / 2);
    const uint32_t* w3e = g_w3t + (size_t)e * FDIM * (HDIM / 2);

    // per-thread staging: A 4 chunks + B 4 chunks of 16B
    int a_row[4], a_c4[4];
    const uint32_t* b_src[4];
    uint32_t a_dst[4], b_dst[4];
#pragma unroll
    for (int u = 0; u < 4; u++) {
        int idx = tid + 128 * u;            // 0..511
        a_row[u] = idx >> 2;
        a_c4 [u] = idx & 3;
        a_dst[u] = sptr(sm + a_row[u] * 20 + a_c4[u] * 4);
        int m = idx >> 8, rem = idx & 255;  // m: 0 = w1, 1 = w3
        int n = rem >> 2, c4 = rem & 3;
        b_src[u] = ((m == 0) ? w1e : w3e) + (size_t)(n0 + n) * (HDIM / 2) + c4 * 4;
        b_dst[u] = sptr(sm + F1_AST + (m * 64 + n) * 20 + c4 * 4);
    }

    int warp = tid >> 5, lane = tid & 31;
    int wm = warp >> 1, wn = warp & 1;      // 2x2 warps, warp tile 64(M) x 32(N)
    int g = lane >> 2, tg = lane & 3;

    float accA[4][4][4], accB[4][4][4];
#pragma unroll
    for (int mi = 0; mi < 4; mi++)
#pragma unroll
        for (int ni = 0; ni < 4; ni++)
#pragma unroll
            for (int q = 0; q < 4; q++) { accA[mi][ni][q] = 0.f; accB[mi][ni][q] = 0.f; }

#pragma unroll
    for (int t = 0; t < 2; t++) {
        int k0 = t * 16;                     // u32 units per K-tile (32 halves)
        uint32_t off = t * F1_STG * 4;
#pragma unroll
        for (int u = 0; u < 4; u++) {
            CP16(a_dst[u] + off, g_xh + (size_t)s_tok[a_row[u]] * (HDIM / 2) + k0 + a_c4[u] * 4);
            CP16(b_dst[u] + off, b_src[u] + k0);
        }
        CP_COMMIT();
    }

    const int NT = HDIM / 32;
#pragma unroll 1
    for (int t = 0; t < NT; t++) {
        CP_WAIT1();
        __syncthreads();
        int p = t & 1;
        const uint32_t* As = sm + p * F1_STG;
        const uint32_t* Bs = As + F1_AST;

#pragma unroll
        for (int kk = 0; kk < 2; kk++) {
            uint32_t a[4][4];
#pragma unroll
            for (int mi = 0; mi < 4; mi++) {
                int r = wm * 64 + mi * 16;
                a[mi][0] = As[(r + g)     * 20 + tg     + kk * 8];
                a[mi][1] = As[(r + 8 + g) * 20 + tg     + kk * 8];
                a[mi][2] = As[(r + g)     * 20 + tg + 4 + kk * 8];
                a[mi][3] = As[(r + 8 + g) * 20 + tg + 4 + kk * 8];
            }
#pragma unroll
            for (int ni = 0; ni < 4; ni++) {
                int n = wn * 32 + ni * 8 + g;
                uint32_t b0 = Bs[n        * 20 + tg     + kk * 8];
                uint32_t b1 = Bs[n        * 20 + tg + 4 + kk * 8];
                uint32_t c0 = Bs[(64 + n) * 20 + tg     + kk * 8];
                uint32_t c1 = Bs[(64 + n) * 20 + tg + 4 + kk * 8];
#pragma unroll
                for (int mi = 0; mi < 4; mi++) {
                    mma_f16(accA[mi][ni][0], accA[mi][ni][1], accA[mi][ni][2], accA[mi][ni][3],
                            a[mi][0], a[mi][1], a[mi][2], a[mi][3], b0, b1);
                    mma_f16(accB[mi][ni][0], accB[mi][ni][1], accB[mi][ni][2], accB[mi][ni][3],
                            a[mi][0], a[mi][1], a[mi][2], a[mi][3], c0, c1);
                }
            }
        }
        __syncthreads();

        int tn = t + 2;
        if (tn < NT) {
            int k0 = tn * 16;
            uint32_t off = p * F1_STG * 4;
#pragma unroll
            for (int u = 0; u < 4; u++) {
                CP16(a_dst[u] + off, g_xh + (size_t)s_tok[a_row[u]] * (HDIM / 2) + k0 + a_c4[u] * 4);
                CP16(b_dst[u] + off, b_src[u] + k0);
            }
        }
        CP_COMMIT();
    }

    // epilogue: h = silu(a*b) stored as fp16 (half2 per u32)
#pragma unroll
    for (int mi = 0; mi < 4; mi++) {
#pragma unroll
        for (int ni = 0; ni < 4; ni++) {
            int rbase = row0 + wm * 64 + mi * 16 + g;
            int cbase = n0 + wn * 32 + ni * 8 + tg * 2;   // even
#pragma unroll
            for (int h = 0; h < 2; h++) {
                int r = rbase + h * 8;
                float p0 = accA[mi][ni][h * 2 + 0] * accB[mi][ni][h * 2 + 0];
                float p1 = accA[mi][ni][h * 2 + 1] * accB[mi][ni][h * 2 + 1];
                float s0 = p0 / (1.f + expf(-p0));
                float s1 = p1 / (1.f + expf(-p1));
                hout[(size_t)r * (FDIM / 2) + cbase / 2] = packh2(s0, s1);
            }
        }
    }
}

// ---------------- kernel 4: GEMM2 fp16 — warp 64x64 + red.v2 weighted scatter ----------------
#define F2_AST 2560            // 128*20
#define F2_BST 2560            // 128*20
#define F2_STG (F2_AST + F2_BST)
#define F2_SMEM (2 * F2_STG * 4)

__global__ __launch_bounds__(128, 2) void k_ffn2(float* __restrict__ out) {
    extern __shared__ uint32_t sm[];
    __shared__ int   s_tok[128];
    __shared__ float s_wgt[128];

    int e    = blockIdx.z;
    int row0 = blockIdx.x * 128;
    int n0   = blockIdx.y * 128;
    int ne   = min(g_cnt[e], CAP);
    if (row0 >= ne) return;

    int tid = threadIdx.x;
    s_tok[tid] = g_tok[e * CAPP + row0 + tid];
    s_wgt[tid] = g_wgt[e * CAPP + row0 + tid];
    __syncthreads();

    const uint32_t* hin = g_h   + (size_t)e * CAPP * (FDIM / 2);
    const uint32_t* w2e = g_w2t + (size_t)e * HDIM * (FDIM / 2);

    const uint32_t* a_src[4];
    uint32_t a_dst[4];
    const uint32_t* b_src[4];
    uint32_t b_dst[4];
#pragma unroll
    for (int u = 0; u < 4; u++) {
        int idx = tid + 128 * u;            // 0..511
        int row = idx >> 2, c4 = idx & 3;
        a_src[u] = hin + (size_t)(row0 + row) * (FDIM / 2) + c4 * 4;
        a_dst[u] = sptr(sm + row * 20 + c4 * 4);
        b_src[u] = w2e + (size_t)(n0 + row) * (FDIM / 2) + c4 * 4;
        b_dst[u] = sptr(sm + F2_AST + row * 20 + c4 * 4);
    }

    int warp = tid >> 5, lane = tid & 31;
    int wm = warp >> 1, wn = warp & 1;      // warp tile 64(M) x 64(N)
    int g = lane >> 2, tg = lane & 3;

    float acc[4][8][4];
#pragma unroll
    for (int mi = 0; mi < 4; mi++)
#pragma unroll
        for (int ni = 0; ni < 8; ni++)
#pragma unroll
            for (int q = 0; q < 4; q++) acc[mi][ni][q] = 0.f;

#pragma unroll
    for (int t = 0; t < 2; t++) {
        int k0 = t * 16;
        uint32_t off = t * F2_STG * 4;
#pragma unroll
        for (int u = 0; u < 4; u++) {
            CP16(a_dst[u] + off, a_src[u] + k0);
            CP16(b_dst[u] + off, b_src[u] + k0);
        }
        CP_COMMIT();
    }

    const int NT = FDIM / 32;   // 8
#pragma unroll 1
    for (int t = 0; t < NT; t++) {
        CP_WAIT1();
        __syncthreads();
        int p = t & 1;
        const uint32_t* As = sm + p * F2_STG;
        const uint32_t* Bs = As + F2_AST;

#pragma unroll
        for (int kk = 0; kk < 2; kk++) {
            uint32_t a[4][4];
#pragma unroll
            for (int mi = 0; mi < 4; mi++) {
                int r = wm * 64 + mi * 16;
                a[mi][0] = As[(r + g)     * 20 + tg     + kk * 8];
                a[mi][1] = As[(r + 8 + g) * 20 + tg     + kk * 8];
                a[mi][2] = As[(r + g)     * 20 + tg + 4 + kk * 8];
                a[mi][3] = As[(r + 8 + g) * 20 + tg + 4 + kk * 8];
            }
#pragma unroll
            for (int ni = 0; ni < 8; ni++) {
                int n = wn * 64 + ni * 8 + g;
                uint32_t b0 = Bs[n * 20 + tg     + kk * 8];
                uint32_t b1 = Bs[n * 20 + tg + 4 + kk * 8];
#pragma unroll
                for (int mi = 0; mi < 4; mi++)
                    mma_f16(acc[mi][ni][0], acc[mi][ni][1], acc[mi][ni][2], acc[mi][ni][3],
                            a[mi][0], a[mi][1], a[mi][2], a[mi][3], b0, b1);
            }
        }
        __syncthreads();

        int tn = t + 2;
        if (tn < NT) {
            int k0 = tn * 16;
            uint32_t off = p * F2_STG * 4;
#pragma unroll
            for (int u = 0; u < 4; u++) {
                CP16(a_dst[u] + off, a_src[u] + k0);
                CP16(b_dst[u] + off, b_src[u] + k0);
            }
        }
        CP_COMMIT();
    }

    // epilogue: weighted scatter via vectorized no-return reductions
#pragma unroll
    for (int mi = 0; mi < 4; mi++) {
#pragma unroll
        for (int ni = 0; ni < 8; ni++) {
            int cbase = n0 + wn * 64 + ni * 8 + tg * 2;
#pragma unroll
            for (int hh = 0; hh < 2; hh++) {
                int rl = wm * 64 + mi * 16 + g + hh * 8;
                float w = s_wgt[rl];
                if (w != 0.f) {
                    int tok = s_tok[rl];
                    red_add_v2(&out[(size_t)tok * HDIM + cbase],
                               acc[mi][ni][hh * 2 + 0] * w,
                               acc[mi][ni][hh * 2 + 1] * w);
                }
            }
        }
    }
}

// ---------------- launch ----------------
extern "C" void kernel_launch(void* const* d_in, const int* in_sizes, int n_in,
                              void* d_out, int out_size) {
    const float* x  = nullptr;
    const float* gw = nullptr;
    const float* wbig[3] = {nullptr, nullptr, nullptr};
    int nbig = 0;
    for (int i = 0; i < n_in; i++) {
        long long sz = in_sizes[i];
        if (sz == (long long)T_TOK * HDIM)      x = (const float*)d_in[i];
        else if (sz == (long long)NEXP * HDIM)  gw = (const float*)d_in[i];
        else if (nbig < 3)                      wbig[nbig++] = (const float*)d_in[i];
    }
    const float* w1 = wbig[0];
    const float* w2 = wbig[1];
    const float* w3 = wbig[2];
    float* out = (float*)d_out;

    cudaFuncSetAttribute(k_ffn1, cudaFuncAttributeMaxDynamicSharedMemorySize, F1_SMEM);
    cudaFuncSetAttribute(k_ffn2, cudaFuncAttributeMaxDynamicSharedMemorySize, F2_SMEM);

    uint32_t* w1t; cudaGetSymbolAddress((void**)&w1t, g_w1t);
    uint32_t* w2t; cudaGetSymbolAddress((void**)&w2t, g_w2t);
    uint32_t* w3t; cudaGetSymbolAddress((void**)&w3t, g_w3t);

    int wn8 = NEXP * FDIM * HDIM / 8;

    // launch index 3 (k_ffn1) is the one ncu captures
    k_cvt_all<<<(3 * wn8 + 255) / 256, 256>>>(
        (const float4*)w1, (uint4*)w1t,
        (const float4*)w2, (uint4*)w2t,
        (const float4*)w3, (uint4*)w3t, wn8);                                   // 0
    k_gate<<<T_TOK / 8, 256>>>(x, gw, (float4*)out);                            // 1
    k_scan_par<<<SCAN_B, SCAN_T>>>();                                           // 2
    k_ffn1<<<dim3(CAPP / 128, FDIM / 64, NEXP), 128, F1_SMEM>>>();              // 3 <- profiled
    k_ffn2<<<dim3(CAPP / 128, HDIM / 128, NEXP), 128, F2_SMEM>>>(out);          // 4
}